// round 1
// baseline (speedup 1.0000x reference)
#include <cuda_runtime.h>
#include <cuda_bf16.h>
#include <cstdint>

// Problem constants (fixed by reference setup_inputs)
constexpr int B = 2, C = 2, D = 160, H = 192, W = 224;
constexpr int DHW = D * H * W;           // 6,881,280
constexpr long long TOTAL = (long long)B * DHW;  // 13,762,560 spatial points

__global__ __launch_bounds__(256)
void affine_grid_sample_kernel(const float* __restrict__ src,
                               const float* __restrict__ mat,
                               float* __restrict__ out)
{
    int idx = blockIdx.x * blockDim.x + threadIdx.x;
    if (idx >= TOTAL) return;

    int b = idx / DHW;
    int s = idx - b * DHW;
    int w =  s % W;
    int t =  s / W;
    int h =  t % H;
    int d =  t / H;

    // normalized coords (align_corners=True): -1 .. +1 inclusive
    float x = fmaf((float)w, 2.0f / (W - 1), -1.0f);
    float y = fmaf((float)h, 2.0f / (H - 1), -1.0f);
    float z = fmaf((float)d, 2.0f / (D - 1), -1.0f);

    // theta = mat with translation column divided by (D, H, W) per row
    const float* m = mat + b * 12;
    float m0  = __ldg(m + 0),  m1  = __ldg(m + 1),  m2  = __ldg(m + 2),  m3  = __ldg(m + 3);
    float m4  = __ldg(m + 4),  m5  = __ldg(m + 5),  m6  = __ldg(m + 6),  m7  = __ldg(m + 7);
    float m8  = __ldg(m + 8),  m9  = __ldg(m + 9),  m10 = __ldg(m + 10), m11 = __ldg(m + 11);

    float gx = fmaf(m0, x, fmaf(m1,  y, fmaf(m2,  z, m3  * (1.0f / D))));
    float gy = fmaf(m4, x, fmaf(m5,  y, fmaf(m6,  z, m7  * (1.0f / H))));
    float gz = fmaf(m8, x, fmaf(m9,  y, fmaf(m10, z, m11 * (1.0f / W))));

    // unnormalize
    float ix = (gx + 1.0f) * (0.5f * (W - 1));
    float iy = (gy + 1.0f) * (0.5f * (H - 1));
    float iz = (gz + 1.0f) * (0.5f * (D - 1));

    float fx0 = floorf(ix), fy0 = floorf(iy), fz0 = floorf(iz);
    float fx = ix - fx0, fy = iy - fy0, fz = iz - fz0;
    int x0 = (int)fx0, y0 = (int)fy0, z0 = (int)fz0;

    const float* sb = src + (size_t)b * C * DHW;

    float acc0 = 0.0f, acc1 = 0.0f;

#pragma unroll
    for (int dz = 0; dz < 2; ++dz) {
        int  zc = z0 + dz;
        bool vz = (zc >= 0) & (zc < D);
        float wz = dz ? fz : (1.0f - fz);
#pragma unroll
        for (int dy = 0; dy < 2; ++dy) {
            int  yc = y0 + dy;
            bool vy = (yc >= 0) & (yc < H);
            float wzy = wz * (dy ? fy : (1.0f - fy));
            int rowbase = (zc * H + yc) * W;
#pragma unroll
            for (int dx = 0; dx < 2; ++dx) {
                int  xc = x0 + dx;
                bool v  = vz & vy & (xc >= 0) & (xc < W);
                float wt = wzy * (dx ? fx : (1.0f - fx));
                if (v) {
                    int lin = rowbase + xc;
                    acc0 = fmaf(wt, __ldg(sb + lin),        acc0);
                    acc1 = fmaf(wt, __ldg(sb + lin + DHW),  acc1);
                }
            }
        }
    }

    size_t ob = (size_t)b * C * DHW + s;
    out[ob]        = acc0;
    out[ob + DHW]  = acc1;
}

extern "C" void kernel_launch(void* const* d_in, const int* in_sizes, int n_in,
                              void* d_out, int out_size)
{
    const float* src = (const float*)d_in[0];
    const float* mat = (const float*)d_in[1];
    float* out = (float*)d_out;

    int threads = 256;
    int blocks = (int)((TOTAL + threads - 1) / threads);
    affine_grid_sample_kernel<<<blocks, threads>>>(src, mat, out);
}

// round 2
// speedup vs baseline: 1.0958x; 1.0958x over previous
#include <cuda_runtime.h>
#include <cuda_bf16.h>
#include <cstdint>

// Problem constants (fixed by reference setup_inputs)
constexpr int B = 2, C = 2, D = 160, H = 192, W = 224;
constexpr int HW  = H * W;          // 43008
constexpr int DHW = D * H * W;      // 6,881,280

__global__ __launch_bounds__(W)
void affine_grid_sample_kernel(const float* __restrict__ src,
                               const float* __restrict__ mat,
                               float* __restrict__ out)
{
    const int w  = threadIdx.x;      // 0..W-1
    const int h  = blockIdx.y;       // 0..H-1
    const int zz = blockIdx.z;       // 0..B*D-1
    const int b  = (zz >= D) ? 1 : 0;
    const int d  = zz - (b ? D : 0);

    // mat row-major [b,3,4]; 48-byte stride keeps 16B alignment per batch
    const float4* m4 = (const float4*)(mat + b * 12);
    const float4 r0 = __ldg(m4 + 0);
    const float4 r1 = __ldg(m4 + 1);
    const float4 r2 = __ldg(m4 + 2);

    // normalized coords (align_corners=True)
    const float x = fmaf((float)w, 2.0f / (W - 1), -1.0f);
    const float y = fmaf((float)h, 2.0f / (H - 1), -1.0f);
    const float z = fmaf((float)d, 2.0f / (D - 1), -1.0f);

    // theta = mat with translation column scaled by 1/{D,H,W} per row
    const float gx = fmaf(r0.x, x, fmaf(r0.y, y, fmaf(r0.z, z, r0.w * (1.0f / D))));
    const float gy = fmaf(r1.x, x, fmaf(r1.y, y, fmaf(r1.z, z, r1.w * (1.0f / H))));
    const float gz = fmaf(r2.x, x, fmaf(r2.y, y, fmaf(r2.z, z, r2.w * (1.0f / W))));

    // unnormalize
    const float ix = (gx + 1.0f) * (0.5f * (W - 1));
    const float iy = (gy + 1.0f) * (0.5f * (H - 1));
    const float iz = (gz + 1.0f) * (0.5f * (D - 1));

    const float fx0 = floorf(ix), fy0 = floorf(iy), fz0 = floorf(iz);
    const float fx = ix - fx0, fy = iy - fy0, fz = iz - fz0;
    const int x0 = (int)fx0, y0 = (int)fy0, z0 = (int)fz0;

    // validity per axis (unsigned-compare trick handles negatives)
    const bool vx0 = (unsigned)x0       < (unsigned)W;
    const bool vx1 = (unsigned)(x0 + 1) < (unsigned)W;
    const bool vy0 = (unsigned)y0       < (unsigned)H;
    const bool vy1 = (unsigned)(y0 + 1) < (unsigned)H;
    const bool vz0 = (unsigned)z0       < (unsigned)D;
    const bool vz1 = (unsigned)(z0 + 1) < (unsigned)D;

    // trilinear weights
    const float wx1 = fx, wx0 = 1.0f - fx;
    const float wy1 = fy, wy0 = 1.0f - fy;
    const float wz1 = fz, wz0 = 1.0f - fz;
    const float w00 = wz0 * wy0, w01 = wz0 * wy1;
    const float w10 = wz1 * wy0, w11 = wz1 * wy1;
    const float w000 = w00 * wx0, w001 = w00 * wx1;
    const float w010 = w01 * wx0, w011 = w01 * wx1;
    const float w100 = w10 * wx0, w101 = w10 * wx1;
    const float w110 = w11 * wx0, w111 = w11 * wx1;

    // single base; taps are immediate offsets folded into LDG
    const float* sb = src + (size_t)b * (size_t)(C * DHW);
    const float* p  = sb + ((size_t)((z0 * H + y0) * W + x0));

    const bool p000 = vz0 & vy0 & vx0, p001 = vz0 & vy0 & vx1;
    const bool p010 = vz0 & vy1 & vx0, p011 = vz0 & vy1 & vx1;
    const bool p100 = vz1 & vy0 & vx0, p101 = vz1 & vy0 & vx1;
    const bool p110 = vz1 & vy1 & vx0, p111 = vz1 & vy1 & vx1;

    // channel 0
    float a000 = p000 ? __ldg(p)              : 0.0f;
    float a001 = p001 ? __ldg(p + 1)          : 0.0f;
    float a010 = p010 ? __ldg(p + W)          : 0.0f;
    float a011 = p011 ? __ldg(p + W + 1)      : 0.0f;
    float a100 = p100 ? __ldg(p + HW)         : 0.0f;
    float a101 = p101 ? __ldg(p + HW + 1)     : 0.0f;
    float a110 = p110 ? __ldg(p + HW + W)     : 0.0f;
    float a111 = p111 ? __ldg(p + HW + W + 1) : 0.0f;
    // channel 1 (same taps, +DHW)
    const float* q = p + DHW;
    float c000 = p000 ? __ldg(q)              : 0.0f;
    float c001 = p001 ? __ldg(q + 1)          : 0.0f;
    float c010 = p010 ? __ldg(q + W)          : 0.0f;
    float c011 = p011 ? __ldg(q + W + 1)      : 0.0f;
    float c100 = p100 ? __ldg(q + HW)         : 0.0f;
    float c101 = p101 ? __ldg(q + HW + 1)     : 0.0f;
    float c110 = p110 ? __ldg(q + HW + W)     : 0.0f;
    float c111 = p111 ? __ldg(q + HW + W + 1) : 0.0f;

    float acc0 = w000 * a000;
    acc0 = fmaf(w001, a001, acc0);
    acc0 = fmaf(w010, a010, acc0);
    acc0 = fmaf(w011, a011, acc0);
    acc0 = fmaf(w100, a100, acc0);
    acc0 = fmaf(w101, a101, acc0);
    acc0 = fmaf(w110, a110, acc0);
    acc0 = fmaf(w111, a111, acc0);

    float acc1 = w000 * c000;
    acc1 = fmaf(w001, c001, acc1);
    acc1 = fmaf(w010, c010, acc1);
    acc1 = fmaf(w011, c011, acc1);
    acc1 = fmaf(w100, c100, acc1);
    acc1 = fmaf(w101, c101, acc1);
    acc1 = fmaf(w110, c110, acc1);
    acc1 = fmaf(w111, c111, acc1);

    const size_t ob = (size_t)b * (size_t)(C * DHW) + (size_t)((d * H + h) * W + w);
    out[ob]       = acc0;
    out[ob + DHW] = acc1;
}

extern "C" void kernel_launch(void* const* d_in, const int* in_sizes, int n_in,
                              void* d_out, int out_size)
{
    const float* src = (const float*)d_in[0];
    const float* mat = (const float*)d_in[1];
    float* out = (float*)d_out;

    dim3 block(W, 1, 1);          // 224 threads = 7 warps
    dim3 grid(1, H, B * D);       // (1, 192, 320)
    affine_grid_sample_kernel<<<grid, block>>>(src, mat, out);
}